// round 1
// baseline (speedup 1.0000x reference)
#include <cuda_runtime.h>
#include <math.h>

#define NN 100000
#define EE 3200000
#define FMAX 176
#define SCAN_NB 98   // ceil(100000/1024)

// ---------------- scratch (static device globals; no allocation) -------------
__device__ __align__(16) float g_h[(size_t)NN * FMAX];    // current node features
__device__ __align__(16) float g_agg[(size_t)NN * FMAX];  // aggregated features
__device__ float g_coef[EE];
__device__ float g_ns[NN];
__device__ float g_nd[NN];
__device__ int   g_deg_in[NN];
__device__ int   g_deg_out[NN];
__device__ int   g_rowptr[NN + 1];
__device__ int   g_cursor[NN];
__device__ int   g_csr_src[EE];
__device__ float g_csr_coef[EE];
__device__ int   g_bsums[128];
__device__ float g_mean[FMAX];

// ---------------- preprocessing ---------------------------------------------
__global__ void k_zero() {
    int i = blockIdx.x * blockDim.x + threadIdx.x;
    if (i < NN) { g_deg_in[i] = 0; g_deg_out[i] = 0; }
    if (i < FMAX) g_mean[i] = 0.f;
}

__global__ void k_deg(const int* __restrict__ src, const int* __restrict__ dst) {
    int e = blockIdx.x * blockDim.x + threadIdx.x;
    if (e < EE) {
        atomicAdd(&g_deg_out[src[e]], 1);
        atomicAdd(&g_deg_in[dst[e]], 1);
    }
}

__global__ void k_norm() {
    int i = blockIdx.x * blockDim.x + threadIdx.x;
    if (i < NN) {
        int o = g_deg_out[i];
        g_ns[i] = (o > 0) ? rsqrtf((float)o) : 0.f;
        int d = g_deg_in[i];
        g_nd[i] = (d > 0) ? rsqrtf((float)d) : 0.f;
    }
}

__global__ void k_coef(const int* __restrict__ src, const float* __restrict__ edata,
                       const float* __restrict__ mu, const float* __restrict__ sigma) {
    int e = blockIdx.x * blockDim.x + threadIdx.x;
    if (e < EE) {
        float ed = edata[e];
        float m = *mu, sg = *sigma;
        float w = (ed == 1.0f) ? 1.0f : expf(-((ed - m) * (ed - m)) / sg);
        g_coef[e] = g_ns[src[e]] * w;
    }
}

// exclusive scan of deg_in -> rowptr (3 kernels)
__global__ void k_scan1() {
    __shared__ int s[1024];
    int i = blockIdx.x * 1024 + threadIdx.x;
    int v = (i < NN) ? g_deg_in[i] : 0;
    s[threadIdx.x] = v;
    __syncthreads();
    for (int off = 1; off < 1024; off <<= 1) {
        int t = 0;
        if (threadIdx.x >= off) t = s[threadIdx.x - off];
        __syncthreads();
        s[threadIdx.x] += t;
        __syncthreads();
    }
    if (i < NN) g_rowptr[i] = s[threadIdx.x] - v;  // exclusive
    if (threadIdx.x == 1023) g_bsums[blockIdx.x] = s[1023];
}

__global__ void k_scan2(int nb) {
    if (threadIdx.x == 0 && blockIdx.x == 0) {
        int acc = 0;
        for (int b = 0; b < nb; b++) { int v = g_bsums[b]; g_bsums[b] = acc; acc += v; }
    }
}

__global__ void k_scan3() {
    int i = blockIdx.x * blockDim.x + threadIdx.x;
    if (i < NN) {
        int r = g_rowptr[i] + g_bsums[i >> 10];
        g_rowptr[i] = r;
        g_cursor[i] = r;
    }
    if (i == 0) g_rowptr[NN] = EE;
}

__global__ void k_scatter(const int* __restrict__ src, const int* __restrict__ dst) {
    int e = blockIdx.x * blockDim.x + threadIdx.x;
    if (e < EE) {
        int d = dst[e];
        int p = atomicAdd(&g_cursor[d], 1);
        g_csr_src[p] = src[e];
        g_csr_coef[p] = g_coef[e];
    }
}

__global__ void k_copyx(const float* __restrict__ x) {
    size_t i = (size_t)blockIdx.x * blockDim.x + threadIdx.x;
    size_t stride = (size_t)gridDim.x * blockDim.x;
    for (; i < (size_t)NN * 64; i += stride) g_h[i] = x[i];
}

// ---------------- aggregation: one warp per dst node --------------------------
// agg[n,:] = nd[n] * sum_{e in in(n)} coef[e] * h[src[e], :]
__global__ void k_spmm(int F) {
    int gw = (blockIdx.x * blockDim.x + threadIdx.x) >> 5;
    int lane = threadIdx.x & 31;
    if (gw >= NN) return;
    int beg = g_rowptr[gw], end = g_rowptr[gw + 1];
    int c0 = lane * 4, c1 = 128 + lane * 4;
    bool p0 = (c0 < F), p1 = (c1 < F);
    float4 a0 = make_float4(0.f, 0.f, 0.f, 0.f);
    float4 a1 = make_float4(0.f, 0.f, 0.f, 0.f);
    for (int e = beg; e < end; e++) {
        int s = g_csr_src[e];
        float cf = g_csr_coef[e];
        const float4* hp = reinterpret_cast<const float4*>(g_h + (size_t)s * F);
        if (p0) {
            float4 v = hp[lane];
            a0.x += cf * v.x; a0.y += cf * v.y; a0.z += cf * v.z; a0.w += cf * v.w;
        }
        if (p1) {
            float4 v = hp[32 + lane];
            a1.x += cf * v.x; a1.y += cf * v.y; a1.z += cf * v.z; a1.w += cf * v.w;
        }
    }
    float nd = g_nd[gw];
    float4* op = reinterpret_cast<float4*>(g_agg + (size_t)gw * F);
    if (p0) {
        a0.x *= nd; a0.y *= nd; a0.z *= nd; a0.w *= nd;
        op[lane] = a0;
    }
    if (p1) {
        a1.x *= nd; a1.y *= nd; a1.z *= nd; a1.w *= nd;
        op[32 + lane] = a1;
    }
}

// ---------------- dense layer: h = leaky_relu(agg @ W + b) --------------------
// A = g_agg [NN x K], B = W [K x Nn], C = g_h [NN x Nn]. K is a multiple of 16.
__global__ void k_gemm(const float* __restrict__ W, const float* __restrict__ bias,
                       int K, int Nn) {
    __shared__ float As[16][65];
    __shared__ float Bs[16][65];
    int tid = threadIdx.x;           // 256 threads
    int tx = tid & 15, ty = tid >> 4;
    int bm = blockIdx.y * 64, bn = blockIdx.x * 64;
    float acc[4][4] = {};
    for (int k0 = 0; k0 < K; k0 += 16) {
        #pragma unroll
        for (int i = 0; i < 4; i++) {
            int l = tid + i * 256;
            // A tile: 64 rows x 16 cols
            int m = l >> 4, kk = l & 15;
            int gm = bm + m;
            As[kk][m] = (gm < NN) ? g_agg[(size_t)gm * K + k0 + kk] : 0.f;
            // B tile: 16 rows x 64 cols
            int kr = l >> 6, nn = l & 63;
            int gn = bn + nn;
            Bs[kr][nn] = (gn < Nn) ? W[(size_t)(k0 + kr) * Nn + gn] : 0.f;
        }
        __syncthreads();
        #pragma unroll
        for (int kk = 0; kk < 16; kk++) {
            float a[4], bb[4];
            #pragma unroll
            for (int i = 0; i < 4; i++) a[i] = As[kk][ty * 4 + i];
            #pragma unroll
            for (int j = 0; j < 4; j++) bb[j] = Bs[kk][tx * 4 + j];
            #pragma unroll
            for (int i = 0; i < 4; i++)
                #pragma unroll
                for (int j = 0; j < 4; j++) acc[i][j] += a[i] * bb[j];
        }
        __syncthreads();
    }
    #pragma unroll
    for (int i = 0; i < 4; i++) {
        int gm = bm + ty * 4 + i;
        if (gm >= NN) continue;
        #pragma unroll
        for (int j = 0; j < 4; j++) {
            int gn = bn + tx * 4 + j;
            if (gn >= Nn) continue;
            float v = acc[i][j] + bias[gn];
            g_h[(size_t)gm * Nn + gn] = (v > 0.f) ? v : 0.01f * v;
        }
    }
}

// ---------------- pooling + head ---------------------------------------------
__global__ void k_mean(int F) {
    int j = threadIdx.x;      // blockDim = F (160)
    float acc = 0.f;
    for (int n = blockIdx.x; n < NN; n += gridDim.x)
        acc += g_h[(size_t)n * F + j];
    atomicAdd(&g_mean[j], acc);
}

__global__ void k_head(const float* __restrict__ Wd1, const float* __restrict__ bd1,
                       const float* __restrict__ Wd2, const float* __restrict__ bd2,
                       float* __restrict__ out) {
    __shared__ float hm[160];
    __shared__ float hd[140];
    int t = threadIdx.x;
    if (t < 160) {
        float v = g_mean[t] / (float)NN;
        hm[t] = (v > 0.f) ? v : 0.01f * v;
    }
    __syncthreads();
    if (t < 140) {
        float s = bd1[t];
        for (int k = 0; k < 160; k++) s += hm[k] * Wd1[k * 140 + t];
        hd[t] = (s > 0.f) ? s : 0.01f * s;
    }
    __syncthreads();
    if (t < 2) {
        float s = bd2[t];
        for (int k = 0; k < 140; k++) s += hd[k] * Wd2[k * 2 + t];
        out[t] = 1.0f / (1.0f + expf(-s));
    }
}

// ---------------- launch ------------------------------------------------------
extern "C" void kernel_launch(void* const* d_in, const int* in_sizes, int n_in,
                              void* d_out, int out_size) {
    const float* x     = (const float*)d_in[0];
    const int*   src   = (const int*)d_in[1];
    const int*   dst   = (const int*)d_in[2];
    const float* edata = (const float*)d_in[3];
    const float* W[11];
    const float* b[11];
    for (int i = 0; i < 11; i++) {
        W[i] = (const float*)d_in[4 + 2 * i];
        b[i] = (const float*)d_in[5 + 2 * i];
    }
    const float* Wd1 = (const float*)d_in[26];
    const float* bd1 = (const float*)d_in[27];
    const float* Wd2 = (const float*)d_in[28];
    const float* bd2 = (const float*)d_in[29];
    const float* mu    = (const float*)d_in[30];
    const float* sigma = (const float*)d_in[31];
    float* out = (float*)d_out;

    static const int dims[12] = {64, 80, 160, 112, 160, 176, 96, 144, 96, 128, 96, 160};

    k_zero<<<(NN + 255) / 256, 256>>>();
    k_deg<<<(EE + 255) / 256, 256>>>(src, dst);
    k_norm<<<(NN + 255) / 256, 256>>>();
    k_coef<<<(EE + 255) / 256, 256>>>(src, edata, mu, sigma);
    k_scan1<<<SCAN_NB, 1024>>>();
    k_scan2<<<1, 32>>>(SCAN_NB);
    k_scan3<<<(NN + 255) / 256, 256>>>();
    k_scatter<<<(EE + 255) / 256, 256>>>(src, dst);
    k_copyx<<<4096, 256>>>(x);

    for (int i = 0; i < 11; i++) {
        int Fi = dims[i], Fo = dims[i + 1];
        k_spmm<<<(NN + 7) / 8, 256>>>(Fi);
        dim3 grid((Fo + 63) / 64, (NN + 63) / 64);
        k_gemm<<<grid, 256>>>(W[i], b[i], Fi, Fo);
    }

    k_mean<<<512, 160>>>(160);
    k_head<<<1, 160>>>(Wd1, bd1, Wd2, bd2, out);
}

// round 3
// speedup vs baseline: 1.1091x; 1.1091x over previous
#include <cuda_runtime.h>
#include <cuda_fp16.h>
#include <math.h>

#define NN 100000
#define EE 3200000
#define FMAX 176
#define SCAN_NB 98   // ceil(100000/1024)

// ---------------- scratch (static device globals; no allocation) -------------
__device__ __align__(16) float  g_h[(size_t)NN * FMAX];    // fp32 node features
__device__ __align__(16) float  g_agg[(size_t)NN * FMAX];  // aggregated features
__device__ __align__(16) __half g_hh0[(size_t)NN * FMAX];  // fp16 features (current)
__device__ __align__(16) __half g_hh1[(size_t)NN * FMAX];  // fp16 scratch (z in gemm-first)
__device__ float g_coef[EE];
__device__ float g_ns[NN];
__device__ float g_nd[NN];
__device__ int   g_deg_in[NN];
__device__ int   g_deg_out[NN];
__device__ int   g_rowptr[NN + 1];
__device__ int   g_cursor[NN];
__device__ int   g_csr_src[EE];
__device__ float g_csr_coef[EE];
__device__ int   g_bsums[128];
__device__ float g_mean[FMAX];

// ---------------- preprocessing ---------------------------------------------
__global__ void k_zero() {
    int i = blockIdx.x * blockDim.x + threadIdx.x;
    if (i < NN) { g_deg_in[i] = 0; g_deg_out[i] = 0; }
    if (i < FMAX) g_mean[i] = 0.f;
}

__global__ void k_deg(const int* __restrict__ src, const int* __restrict__ dst) {
    int e = blockIdx.x * blockDim.x + threadIdx.x;
    if (e < EE) {
        atomicAdd(&g_deg_out[src[e]], 1);
        atomicAdd(&g_deg_in[dst[e]], 1);
    }
}

__global__ void k_norm() {
    int i = blockIdx.x * blockDim.x + threadIdx.x;
    if (i < NN) {
        int o = g_deg_out[i];
        g_ns[i] = (o > 0) ? rsqrtf((float)o) : 0.f;
        int d = g_deg_in[i];
        g_nd[i] = (d > 0) ? rsqrtf((float)d) : 0.f;
    }
}

__global__ void k_coef(const int* __restrict__ src, const float* __restrict__ edata,
                       const float* __restrict__ mu, const float* __restrict__ sigma) {
    int e = blockIdx.x * blockDim.x + threadIdx.x;
    if (e < EE) {
        float ed = edata[e];
        float m = *mu, sg = *sigma;
        float w = (ed == 1.0f) ? 1.0f : expf(-((ed - m) * (ed - m)) / sg);
        g_coef[e] = g_ns[src[e]] * w;
    }
}

// exclusive scan of deg_in -> rowptr (3 kernels)
__global__ void k_scan1() {
    __shared__ int s[1024];
    int i = blockIdx.x * 1024 + threadIdx.x;
    int v = (i < NN) ? g_deg_in[i] : 0;
    s[threadIdx.x] = v;
    __syncthreads();
    for (int off = 1; off < 1024; off <<= 1) {
        int t = 0;
        if (threadIdx.x >= off) t = s[threadIdx.x - off];
        __syncthreads();
        s[threadIdx.x] += t;
        __syncthreads();
    }
    if (i < NN) g_rowptr[i] = s[threadIdx.x] - v;  // exclusive
    if (threadIdx.x == 1023) g_bsums[blockIdx.x] = s[1023];
}

__global__ void k_scan2(int nb) {
    if (threadIdx.x == 0 && blockIdx.x == 0) {
        int acc = 0;
        for (int b = 0; b < nb; b++) { int v = g_bsums[b]; g_bsums[b] = acc; acc += v; }
    }
}

__global__ void k_scan3() {
    int i = blockIdx.x * blockDim.x + threadIdx.x;
    if (i < NN) {
        int r = g_rowptr[i] + g_bsums[i >> 10];
        g_rowptr[i] = r;
        g_cursor[i] = r;
    }
    if (i == 0) g_rowptr[NN] = EE;
}

__global__ void k_scatter(const int* __restrict__ src, const int* __restrict__ dst) {
    int e = blockIdx.x * blockDim.x + threadIdx.x;
    if (e < EE) {
        int d = dst[e];
        int p = atomicAdd(&g_cursor[d], 1);
        g_csr_src[p] = src[e];
        g_csr_coef[p] = g_coef[e];
    }
}

__global__ void k_copyx(const float* __restrict__ x) {
    size_t i = (size_t)blockIdx.x * blockDim.x + threadIdx.x;
    size_t stride = (size_t)gridDim.x * blockDim.x;
    for (; i < (size_t)NN * 64; i += stride) {
        float v = x[i];
        g_h[i] = v;
        g_hh0[i] = __float2half(v);
    }
}

// ---------------- aggregation: one warp per dst node --------------------------
// MODE 0 (spmm-first): read g_hh0, write g_agg = acc*nd (fp32)
// MODE 1 (post-gemm):  read g_hh1 (z), write g_h & g_hh0 = leaky(acc*nd + b)
template<int MODE>
__global__ void k_spmm(int F, const float* __restrict__ bias) {
    int gw = (blockIdx.x * blockDim.x + threadIdx.x) >> 5;
    int lane = threadIdx.x & 31;
    if (gw >= NN) return;
    int beg = g_rowptr[gw], end = g_rowptr[gw + 1];
    int c = lane * 8;
    bool p = (c < F);
    const __half* hsrc = (MODE == 0) ? g_hh0 : g_hh1;
    float acc[8] = {};
    for (int e = beg; e < end; e++) {
        int s = g_csr_src[e];
        float cf = g_csr_coef[e];
        if (p) {
            int4 v = *reinterpret_cast<const int4*>(hsrc + (size_t)s * F + c);
            const __half2* hp = reinterpret_cast<const __half2*>(&v);
            #pragma unroll
            for (int q = 0; q < 4; q++) {
                float2 f = __half22float2(hp[q]);
                acc[2 * q + 0] += cf * f.x;
                acc[2 * q + 1] += cf * f.y;
            }
        }
    }
    if (!p) return;
    float nd = g_nd[gw];
    if (MODE == 0) {
        float4 o0 = make_float4(acc[0] * nd, acc[1] * nd, acc[2] * nd, acc[3] * nd);
        float4 o1 = make_float4(acc[4] * nd, acc[5] * nd, acc[6] * nd, acc[7] * nd);
        float4* op = reinterpret_cast<float4*>(g_agg + (size_t)gw * F + c);
        op[0] = o0; op[1] = o1;
    } else {
        float out[8];
        __half2 ho[4];
        #pragma unroll
        for (int j = 0; j < 8; j++) {
            float v = acc[j] * nd + bias[c + j];
            out[j] = (v > 0.f) ? v : 0.01f * v;
        }
        #pragma unroll
        for (int q = 0; q < 4; q++)
            ho[q] = __floats2half2_rn(out[2 * q], out[2 * q + 1]);
        float4* op = reinterpret_cast<float4*>(g_h + (size_t)gw * F + c);
        op[0] = *reinterpret_cast<float4*>(&out[0]);
        op[1] = *reinterpret_cast<float4*>(&out[4]);
        *reinterpret_cast<int4*>(g_hh0 + (size_t)gw * F + c) = *reinterpret_cast<int4*>(ho);
    }
}

// ---------------- dense layer GEMM: 128x64 tile, 8x4 per thread ---------------
// MODE 0 (post-agg): A = g_agg, C = leaky(A@W + b) -> g_h & g_hh0
// MODE 1 (pre-agg):  A = g_h,   C = A@W            -> g_hh1 only
template<int MODE>
__global__ void k_gemm(const float* __restrict__ W,
                       const float* __restrict__ bias, int K, int Nn) {
    const float* A = (MODE == 0) ? g_agg : g_h;   // device-side symbol ref (valid)
    __shared__ float As[16][132];
    __shared__ float Bs[16][68];
    int tid = threadIdx.x;           // 256 threads
    int bm = blockIdx.y * 128, bn = blockIdx.x * 64;
    int tx = tid & 15, ty = tid >> 4;
    float acc[8][4] = {};
    for (int k0 = 0; k0 < K; k0 += 16) {
        #pragma unroll
        for (int i = 0; i < 2; i++) {
            int f = tid + i * 256;          // float4 index: 512 total
            int m = f >> 2, kq = f & 3;
            int gm = bm + m;
            float4 v = (gm < NN) ? *reinterpret_cast<const float4*>(A + (size_t)gm * K + k0 + kq * 4)
                                 : make_float4(0.f, 0.f, 0.f, 0.f);
            As[kq * 4 + 0][m] = v.x;
            As[kq * 4 + 1][m] = v.y;
            As[kq * 4 + 2][m] = v.z;
            As[kq * 4 + 3][m] = v.w;
        }
        {
            int kr = tid >> 4, nq = tid & 15;
            int gn = bn + nq * 4;
            float4 v = (gn < Nn) ? *reinterpret_cast<const float4*>(W + (size_t)(k0 + kr) * Nn + gn)
                                 : make_float4(0.f, 0.f, 0.f, 0.f);
            *reinterpret_cast<float4*>(&Bs[kr][nq * 4]) = v;
        }
        __syncthreads();
        #pragma unroll
        for (int kk = 0; kk < 16; kk++) {
            float a[8], bb[4];
            *reinterpret_cast<float4*>(&a[0]) = *reinterpret_cast<float4*>(&As[kk][ty * 8]);
            *reinterpret_cast<float4*>(&a[4]) = *reinterpret_cast<float4*>(&As[kk][ty * 8 + 4]);
            *reinterpret_cast<float4*>(&bb[0]) = *reinterpret_cast<float4*>(&Bs[kk][tx * 4]);
            #pragma unroll
            for (int i = 0; i < 8; i++)
                #pragma unroll
                for (int j = 0; j < 4; j++) acc[i][j] += a[i] * bb[j];
        }
        __syncthreads();
    }
    #pragma unroll
    for (int i = 0; i < 8; i++) {
        int gm = bm + ty * 8 + i;
        if (gm >= NN) continue;
        #pragma unroll
        for (int j = 0; j < 4; j++) {
            int gn = bn + tx * 4 + j;
            if (gn >= Nn) continue;
            float v = acc[i][j];
            if (MODE == 0) {
                v += bias[gn];
                v = (v > 0.f) ? v : 0.01f * v;
                g_h[(size_t)gm * Nn + gn] = v;
                g_hh0[(size_t)gm * Nn + gn] = __float2half(v);
            } else {
                g_hh1[(size_t)gm * Nn + gn] = __float2half(v);
            }
        }
    }
}

// ---------------- pooling + head ---------------------------------------------
__global__ void k_mean(int F) {
    int j = threadIdx.x;      // blockDim = F (160)
    float acc = 0.f;
    for (int n = blockIdx.x; n < NN; n += gridDim.x)
        acc += g_h[(size_t)n * F + j];
    atomicAdd(&g_mean[j], acc);
}

__global__ void k_head(const float* __restrict__ Wd1, const float* __restrict__ bd1,
                       const float* __restrict__ Wd2, const float* __restrict__ bd2,
                       float* __restrict__ out) {
    __shared__ float hm[160];
    __shared__ float hd[140];
    int t = threadIdx.x;
    if (t < 160) {
        float v = g_mean[t] / (float)NN;
        hm[t] = (v > 0.f) ? v : 0.01f * v;
    }
    __syncthreads();
    if (t < 140) {
        float s = bd1[t];
        for (int k = 0; k < 160; k++) s += hm[k] * Wd1[k * 140 + t];
        hd[t] = (s > 0.f) ? s : 0.01f * s;
    }
    __syncthreads();
    if (t < 2) {
        float s = bd2[t];
        for (int k = 0; k < 140; k++) s += hd[k] * Wd2[k * 2 + t];
        out[t] = 1.0f / (1.0f + expf(-s));
    }
}

// ---------------- launch ------------------------------------------------------
extern "C" void kernel_launch(void* const* d_in, const int* in_sizes, int n_in,
                              void* d_out, int out_size) {
    const float* x     = (const float*)d_in[0];
    const int*   src   = (const int*)d_in[1];
    const int*   dst   = (const int*)d_in[2];
    const float* edata = (const float*)d_in[3];
    const float* W[11];
    const float* b[11];
    for (int i = 0; i < 11; i++) {
        W[i] = (const float*)d_in[4 + 2 * i];
        b[i] = (const float*)d_in[5 + 2 * i];
    }
    const float* Wd1 = (const float*)d_in[26];
    const float* bd1 = (const float*)d_in[27];
    const float* Wd2 = (const float*)d_in[28];
    const float* bd2 = (const float*)d_in[29];
    const float* mu    = (const float*)d_in[30];
    const float* sigma = (const float*)d_in[31];
    float* out = (float*)d_out;

    static const int dims[12] = {64, 80, 160, 112, 160, 176, 96, 144, 96, 128, 96, 160};
    // gemm-first when F_out < F_in (aggregate the narrower tensor)
    static const int gfirst[11] = {0, 0, 1, 0, 0, 1, 0, 1, 0, 1, 0};

    k_zero<<<(NN + 255) / 256, 256>>>();
    k_deg<<<(EE + 255) / 256, 256>>>(src, dst);
    k_norm<<<(NN + 255) / 256, 256>>>();
    k_coef<<<(EE + 255) / 256, 256>>>(src, edata, mu, sigma);
    k_scan1<<<SCAN_NB, 1024>>>();
    k_scan2<<<1, 32>>>(SCAN_NB);
    k_scan3<<<(NN + 255) / 256, 256>>>();
    k_scatter<<<(EE + 255) / 256, 256>>>(src, dst);
    k_copyx<<<4096, 256>>>(x);

    const int spmm_blocks = (NN * 32 + 255) / 256;   // one warp per node
    for (int i = 0; i < 11; i++) {
        int Fi = dims[i], Fo = dims[i + 1];
        if (gfirst[i]) {
            dim3 grid((Fo + 63) / 64, (NN + 127) / 128);
            k_gemm<1><<<grid, 256>>>(W[i], nullptr, Fi, Fo);
            k_spmm<1><<<spmm_blocks, 256>>>(Fo, b[i]);
        } else {
            k_spmm<0><<<spmm_blocks, 256>>>(Fi, nullptr);
            dim3 grid((Fo + 63) / 64, (NN + 127) / 128);
            k_gemm<0><<<grid, 256>>>(W[i], b[i], Fi, Fo);
        }
    }

    k_mean<<<512, 160>>>(160);
    k_head<<<1, 160>>>(Wd1, bd1, Wd2, bd2, out);
}

// round 4
// speedup vs baseline: 1.5056x; 1.3575x over previous
#include <cuda_runtime.h>
#include <cuda_fp16.h>
#include <math.h>
#include <stdint.h>

#define NN 100000
#define EE 3200000
#define FMAX 176
#define SCAN_NB 98   // ceil(100000/1024)
#define WSTRIDE (176 * 176)

// ---------------- scratch (static device globals; no allocation) -------------
__device__ __align__(16) float  g_h[(size_t)NN * FMAX];    // fp32 (final layer only)
__device__ __align__(16) __half g_hh0[(size_t)NN * FMAX];  // fp16 activations (current)
__device__ __align__(16) __half g_hh1[(size_t)NN * FMAX];  // fp16 intermediate (agg or z)
__device__ __align__(16) __half g_w16[11 * WSTRIDE];       // fp16 weights, [N][K] per layer
__device__ float g_coef[EE];
__device__ float g_ns[NN];
__device__ float g_nd[NN];
__device__ int   g_deg_in[NN];
__device__ int   g_deg_out[NN];
__device__ int   g_rowptr[NN + 1];
__device__ int   g_cursor[NN];
__device__ int   g_csr_src[EE];
__device__ float g_csr_coef[EE];
__device__ int   g_bsums[128];
__device__ float g_mean[FMAX];

// ---------------- preprocessing ---------------------------------------------
__global__ void k_zero() {
    int i = blockIdx.x * blockDim.x + threadIdx.x;
    if (i < NN) { g_deg_in[i] = 0; g_deg_out[i] = 0; }
    if (i < FMAX) g_mean[i] = 0.f;
}

__global__ void k_deg(const int* __restrict__ src, const int* __restrict__ dst) {
    int e = blockIdx.x * blockDim.x + threadIdx.x;
    if (e < EE) {
        atomicAdd(&g_deg_out[src[e]], 1);
        atomicAdd(&g_deg_in[dst[e]], 1);
    }
}

__global__ void k_norm() {
    int i = blockIdx.x * blockDim.x + threadIdx.x;
    if (i < NN) {
        int o = g_deg_out[i];
        g_ns[i] = (o > 0) ? rsqrtf((float)o) : 0.f;
        int d = g_deg_in[i];
        g_nd[i] = (d > 0) ? rsqrtf((float)d) : 0.f;
    }
}

__global__ void k_coef(const int* __restrict__ src, const float* __restrict__ edata,
                       const float* __restrict__ mu, const float* __restrict__ sigma) {
    int e = blockIdx.x * blockDim.x + threadIdx.x;
    if (e < EE) {
        float ed = edata[e];
        float m = *mu, sg = *sigma;
        float w = (ed == 1.0f) ? 1.0f : expf(-((ed - m) * (ed - m)) / sg);
        g_coef[e] = g_ns[src[e]] * w;
    }
}

// exclusive scan of deg_in -> rowptr
__global__ void k_scan1() {
    __shared__ int s[1024];
    int i = blockIdx.x * 1024 + threadIdx.x;
    int v = (i < NN) ? g_deg_in[i] : 0;
    s[threadIdx.x] = v;
    __syncthreads();
    for (int off = 1; off < 1024; off <<= 1) {
        int t = 0;
        if (threadIdx.x >= off) t = s[threadIdx.x - off];
        __syncthreads();
        s[threadIdx.x] += t;
        __syncthreads();
    }
    if (i < NN) g_rowptr[i] = s[threadIdx.x] - v;  // exclusive
    if (threadIdx.x == 1023) g_bsums[blockIdx.x] = s[1023];
}

__global__ void k_scan2(int nb) {
    if (threadIdx.x == 0 && blockIdx.x == 0) {
        int acc = 0;
        for (int b = 0; b < nb; b++) { int v = g_bsums[b]; g_bsums[b] = acc; acc += v; }
    }
}

__global__ void k_scan3() {
    int i = blockIdx.x * blockDim.x + threadIdx.x;
    if (i < NN) {
        int r = g_rowptr[i] + g_bsums[i >> 10];
        g_rowptr[i] = r;
        g_cursor[i] = r;
    }
    if (i == 0) g_rowptr[NN] = EE;
}

__global__ void k_scatter(const int* __restrict__ src, const int* __restrict__ dst) {
    int e = blockIdx.x * blockDim.x + threadIdx.x;
    if (e < EE) {
        int d = dst[e];
        int p = atomicAdd(&g_cursor[d], 1);
        g_csr_src[p] = src[e];
        g_csr_coef[p] = g_coef[e];
    }
}

__global__ void k_copyx(const float* __restrict__ x) {
    size_t i = (size_t)blockIdx.x * blockDim.x + threadIdx.x;
    size_t stride = (size_t)gridDim.x * blockDim.x;
    for (; i < (size_t)NN * 64; i += stride)
        g_hh0[i] = __float2half(x[i]);
}

// ---------------- weight conversion: fp32 [K,N] -> fp16 [N,K] ----------------
struct WConv {
    const float* w[11];
    int K[11];
    int N[11];
};

__global__ void k_wconv(WConv p) {
    int layer = blockIdx.y;
    int K = p.K[layer], N = p.N[layer];
    int tot = K * N;
    const float* w = p.w[layer];
    __half* out = g_w16 + (size_t)layer * WSTRIDE;
    for (int i = blockIdx.x * blockDim.x + threadIdx.x; i < tot; i += gridDim.x * blockDim.x) {
        int k = i / N, n = i % N;
        out[n * K + k] = __float2half(w[i]);
    }
}

// ---------------- aggregation: one warp per dst node --------------------------
// MODE 0 (spmm-first): read g_hh0, write g_hh1 = acc*nd (fp16)
// MODE 1 (post-gemm):  read g_hh1 (z), write g_hh0 = leaky(acc*nd + b) (fp16)
template<int MODE>
__global__ void k_spmm(int F, const float* __restrict__ bias) {
    int gw = (blockIdx.x * blockDim.x + threadIdx.x) >> 5;
    int lane = threadIdx.x & 31;
    if (gw >= NN) return;
    int beg = g_rowptr[gw], end = g_rowptr[gw + 1];
    int c = lane * 8;
    bool p = (c < F);
    const __half* hsrc = (MODE == 0) ? g_hh0 : g_hh1;
    float acc[8] = {};
    for (int e = beg; e < end; e++) {
        int s = g_csr_src[e];
        float cf = g_csr_coef[e];
        if (p) {
            int4 v = *reinterpret_cast<const int4*>(hsrc + (size_t)s * F + c);
            const __half2* hp = reinterpret_cast<const __half2*>(&v);
            #pragma unroll
            for (int q = 0; q < 4; q++) {
                float2 f = __half22float2(hp[q]);
                acc[2 * q + 0] += cf * f.x;
                acc[2 * q + 1] += cf * f.y;
            }
        }
    }
    if (!p) return;
    float nd = g_nd[gw];
    __half2 ho[4];
    if (MODE == 0) {
        #pragma unroll
        for (int q = 0; q < 4; q++)
            ho[q] = __floats2half2_rn(acc[2 * q] * nd, acc[2 * q + 1] * nd);
        *reinterpret_cast<int4*>(g_hh1 + (size_t)gw * F + c) = *reinterpret_cast<int4*>(ho);
    } else {
        #pragma unroll
        for (int j = 0; j < 8; j++) {
            float v = acc[j] * nd + bias[c + j];
            acc[j] = (v > 0.f) ? v : 0.01f * v;
        }
        #pragma unroll
        for (int q = 0; q < 4; q++)
            ho[q] = __floats2half2_rn(acc[2 * q], acc[2 * q + 1]);
        *reinterpret_cast<int4*>(g_hh0 + (size_t)gw * F + c) = *reinterpret_cast<int4*>(ho);
    }
}

// ---------------- tensor-core GEMM (HMMA m16n8k16, fp16 in / fp32 acc) --------
// C[M,N] = A[M,K] @ W[K,N];  A fp16 row-major, W fp16 stored [N,K] (col-major B)
// Block: 128(M) x 64(N), 8 warps as 4x2, warp tile 32x32 = 2x4 mma tiles.
// MODE 0: A = g_hh1, out = leaky(C + bias) -> g_hh0 (+ g_h fp32 if W32)
// MODE 1: A = g_hh0, out = C -> g_hh1

__device__ __forceinline__ void mma16816(float* d, const uint32_t* a, const uint32_t* b) {
    asm volatile(
        "mma.sync.aligned.m16n8k16.row.col.f32.f16.f16.f32 "
        "{%0,%1,%2,%3}, {%4,%5,%6,%7}, {%8,%9}, {%0,%1,%2,%3};\n"
        : "+f"(d[0]), "+f"(d[1]), "+f"(d[2]), "+f"(d[3])
        : "r"(a[0]), "r"(a[1]), "r"(a[2]), "r"(a[3]), "r"(b[0]), "r"(b[1]));
}

#define SA 80  // smem row stride in halves (64 + 16 pad)

template<int MODE, int W32>
__global__ void k_gemm(const float* __restrict__ bias, int layer, int K, int Nn) {
    const __half* A = (MODE == 0) ? g_hh1 : g_hh0;
    const __half* Wl = g_w16 + (size_t)layer * WSTRIDE;
    __shared__ __half As[128 * SA];
    __shared__ __half Bs[64 * SA];

    int tid = threadIdx.x;            // 256
    int lane = tid & 31, wid = tid >> 5;
    int warpM = wid >> 1, warpN = wid & 1;
    int g = lane >> 2, tg2 = (lane & 3) * 2;
    int bm = blockIdx.y * 128, bn = blockIdx.x * 64;

    float acc[2][4][4] = {};

    for (int kc = 0; kc < K; kc += 64) {
        // load A tile: 128 rows x 64 halves = 1024 int4
        #pragma unroll
        for (int t = 0; t < 4; t++) {
            int idx = tid + t * 256;
            int row = idx >> 3, q = idx & 7;
            int gm = bm + row, o = kc + q * 8;
            int4 v = make_int4(0, 0, 0, 0);
            if (gm < NN && o < K)
                v = *reinterpret_cast<const int4*>(A + (size_t)gm * K + o);
            *reinterpret_cast<int4*>(&As[row * SA + q * 8]) = v;
        }
        // load B tile: 64 rows x 64 halves = 512 int4
        #pragma unroll
        for (int t = 0; t < 2; t++) {
            int idx = tid + t * 256;
            int row = idx >> 3, q = idx & 7;
            int gn = bn + row, o = kc + q * 8;
            int4 v = make_int4(0, 0, 0, 0);
            if (gn < Nn && o < K)
                v = *reinterpret_cast<const int4*>(Wl + (size_t)gn * K + o);
            *reinterpret_cast<int4*>(&Bs[row * SA + q * 8]) = v;
        }
        __syncthreads();

        #pragma unroll
        for (int ks = 0; ks < 4; ks++) {
            int kk = ks * 16;
            uint32_t a[2][4], bf[4][2];
            #pragma unroll
            for (int mt = 0; mt < 2; mt++) {
                int r = warpM * 32 + mt * 16 + g;
                a[mt][0] = *reinterpret_cast<const uint32_t*>(&As[r * SA + kk + tg2]);
                a[mt][1] = *reinterpret_cast<const uint32_t*>(&As[(r + 8) * SA + kk + tg2]);
                a[mt][2] = *reinterpret_cast<const uint32_t*>(&As[r * SA + kk + tg2 + 8]);
                a[mt][3] = *reinterpret_cast<const uint32_t*>(&As[(r + 8) * SA + kk + tg2 + 8]);
            }
            #pragma unroll
            for (int nt = 0; nt < 4; nt++) {
                int n = warpN * 32 + nt * 8 + g;
                bf[nt][0] = *reinterpret_cast<const uint32_t*>(&Bs[n * SA + kk + tg2]);
                bf[nt][1] = *reinterpret_cast<const uint32_t*>(&Bs[n * SA + kk + tg2 + 8]);
            }
            #pragma unroll
            for (int mt = 0; mt < 2; mt++)
                #pragma unroll
                for (int nt = 0; nt < 4; nt++)
                    mma16816(acc[mt][nt], a[mt], bf[nt]);
        }
        __syncthreads();
    }

    // epilogue: c0,c1 -> (row, c0..c0+1); c2,c3 -> (row+8, c0..c0+1)
    #pragma unroll
    for (int mt = 0; mt < 2; mt++) {
        #pragma unroll
        for (int nt = 0; nt < 4; nt++) {
            int r0 = bm + warpM * 32 + mt * 16 + g;
            int c0 = bn + warpN * 32 + nt * 8 + tg2;
            float* cc = acc[mt][nt];
            #pragma unroll
            for (int half = 0; half < 2; half++) {
                int r = r0 + half * 8;
                float v0 = cc[half * 2 + 0], v1 = cc[half * 2 + 1];
                if (r < NN && c0 + 1 < Nn) {
                    if (MODE == 0) {
                        v0 += bias[c0]; v1 += bias[c0 + 1];
                        v0 = (v0 > 0.f) ? v0 : 0.01f * v0;
                        v1 = (v1 > 0.f) ? v1 : 0.01f * v1;
                        *reinterpret_cast<__half2*>(g_hh0 + (size_t)r * Nn + c0) =
                            __floats2half2_rn(v0, v1);
                        if (W32) {
                            g_h[(size_t)r * Nn + c0] = v0;
                            g_h[(size_t)r * Nn + c0 + 1] = v1;
                        }
                    } else {
                        *reinterpret_cast<__half2*>(g_hh1 + (size_t)r * Nn + c0) =
                            __floats2half2_rn(v0, v1);
                    }
                }
            }
        }
    }
}

// ---------------- pooling + head ---------------------------------------------
__global__ void k_mean(int F) {
    int j = threadIdx.x;      // blockDim = F (160)
    float acc = 0.f;
    for (int n = blockIdx.x; n < NN; n += gridDim.x)
        acc += g_h[(size_t)n * F + j];
    atomicAdd(&g_mean[j], acc);
}

__global__ void k_head(const float* __restrict__ Wd1, const float* __restrict__ bd1,
                       const float* __restrict__ Wd2, const float* __restrict__ bd2,
                       float* __restrict__ out) {
    __shared__ float hm[160];
    __shared__ float hd[140];
    int t = threadIdx.x;
    if (t < 160) {
        float v = g_mean[t] / (float)NN;
        hm[t] = (v > 0.f) ? v : 0.01f * v;
    }
    __syncthreads();
    if (t < 140) {
        float s = bd1[t];
        for (int k = 0; k < 160; k++) s += hm[k] * Wd1[k * 140 + t];
        hd[t] = (s > 0.f) ? s : 0.01f * s;
    }
    __syncthreads();
    if (t < 2) {
        float s = bd2[t];
        for (int k = 0; k < 140; k++) s += hd[k] * Wd2[k * 2 + t];
        out[t] = 1.0f / (1.0f + expf(-s));
    }
}

// ---------------- launch ------------------------------------------------------
extern "C" void kernel_launch(void* const* d_in, const int* in_sizes, int n_in,
                              void* d_out, int out_size) {
    const float* x     = (const float*)d_in[0];
    const int*   src   = (const int*)d_in[1];
    const int*   dst   = (const int*)d_in[2];
    const float* edata = (const float*)d_in[3];
    const float* W[11];
    const float* b[11];
    for (int i = 0; i < 11; i++) {
        W[i] = (const float*)d_in[4 + 2 * i];
        b[i] = (const float*)d_in[5 + 2 * i];
    }
    const float* Wd1 = (const float*)d_in[26];
    const float* bd1 = (const float*)d_in[27];
    const float* Wd2 = (const float*)d_in[28];
    const float* bd2 = (const float*)d_in[29];
    const float* mu    = (const float*)d_in[30];
    const float* sigma = (const float*)d_in[31];
    float* out = (float*)d_out;

    static const int dims[12] = {64, 80, 160, 112, 160, 176, 96, 144, 96, 128, 96, 160};
    // gemm-first when F_out < F_in (aggregate the narrower tensor)
    static const int gfirst[11] = {0, 0, 1, 0, 0, 1, 0, 1, 0, 1, 0};

    k_zero<<<(NN + 255) / 256, 256>>>();
    k_deg<<<(EE + 255) / 256, 256>>>(src, dst);
    k_norm<<<(NN + 255) / 256, 256>>>();
    k_coef<<<(EE + 255) / 256, 256>>>(src, edata, mu, sigma);
    k_scan1<<<SCAN_NB, 1024>>>();
    k_scan2<<<1, 32>>>(SCAN_NB);
    k_scan3<<<(NN + 255) / 256, 256>>>();
    k_scatter<<<(EE + 255) / 256, 256>>>(src, dst);
    k_copyx<<<4096, 256>>>(x);

    WConv wc;
    for (int i = 0; i < 11; i++) {
        wc.w[i] = W[i];
        wc.K[i] = dims[i];
        wc.N[i] = dims[i + 1];
    }
    k_wconv<<<dim3(121, 11), 256>>>(wc);

    const int spmm_blocks = (NN * 32 + 255) / 256;   // one warp per node
    for (int i = 0; i < 11; i++) {
        int Fi = dims[i], Fo = dims[i + 1];
        dim3 grid((Fo + 63) / 64, (NN + 127) / 128);
        if (gfirst[i]) {
            k_gemm<1, 0><<<grid, 256>>>(nullptr, i, Fi, Fo);
            k_spmm<1><<<spmm_blocks, 256>>>(Fo, b[i]);
        } else {
            k_spmm<0><<<spmm_blocks, 256>>>(Fi, nullptr);
            if (i == 10)
                k_gemm<0, 1><<<grid, 256>>>(b[i], i, Fi, Fo);
            else
                k_gemm<0, 0><<<grid, 256>>>(b[i], i, Fi, Fo);
        }
    }

    k_mean<<<512, 160>>>(160);
    k_head<<<1, 160>>>(Wd1, bd1, Wd2, bd2, out);
}

// round 5
// speedup vs baseline: 2.5160x; 1.6711x over previous
#include <cuda_runtime.h>
#include <cuda_fp16.h>
#include <math.h>
#include <stdint.h>

#define NN 100000
#define EE 3200000
#define FMAX 176
#define SCAN_NB 98   // ceil(100000/1024)
#define WSTRIDE (176 * 176)

// ---------------- scratch (static device globals; no allocation) -------------
__device__ __align__(16) float  g_h[(size_t)NN * FMAX];    // fp32 (final layer only)
__device__ __align__(16) __half g_hh0[(size_t)NN * FMAX];  // fp16 activations (current)
__device__ __align__(16) __half g_hh1[(size_t)NN * FMAX];  // fp16 intermediate (agg or z)
__device__ __align__(16) __half g_w16[11 * WSTRIDE];       // fp16 weights, [N][K] per layer
__device__ float g_ns[NN];
__device__ float g_nd[NN];
__device__ int   g_deg_in[NN];
__device__ int   g_deg_out[NN];
__device__ int   g_rowptr[NN + 1];
__device__ int   g_cursor[NN];
__device__ __align__(8) int2 g_csr[EE];    // (src, coef as float bits)
__device__ int   g_bsums[128];
__device__ float g_mean[FMAX];

// ---------------- preprocessing ---------------------------------------------
__global__ void k_zero() {
    int i = blockIdx.x * blockDim.x + threadIdx.x;
    if (i < NN) { g_deg_in[i] = 0; g_deg_out[i] = 0; }
    if (i < FMAX) g_mean[i] = 0.f;
}

__global__ void k_deg(const int* __restrict__ src, const int* __restrict__ dst) {
    int e = blockIdx.x * blockDim.x + threadIdx.x;
    if (e < EE) {
        atomicAdd(&g_deg_out[src[e]], 1);
        atomicAdd(&g_deg_in[dst[e]], 1);
    }
}

// exclusive scan of deg_in -> rowptr
__global__ void k_scan1() {
    __shared__ int s[1024];
    int i = blockIdx.x * 1024 + threadIdx.x;
    int v = (i < NN) ? g_deg_in[i] : 0;
    s[threadIdx.x] = v;
    __syncthreads();
    for (int off = 1; off < 1024; off <<= 1) {
        int t = 0;
        if (threadIdx.x >= off) t = s[threadIdx.x - off];
        __syncthreads();
        s[threadIdx.x] += t;
        __syncthreads();
    }
    if (i < NN) g_rowptr[i] = s[threadIdx.x] - v;  // exclusive
    if (threadIdx.x == 1023) g_bsums[blockIdx.x] = s[1023];
}

__global__ void k_scan2(int nb) {
    if (threadIdx.x == 0 && blockIdx.x == 0) {
        int acc = 0;
        for (int b = 0; b < nb; b++) { int v = g_bsums[b]; g_bsums[b] = acc; acc += v; }
    }
}

// scan finalize + degree norms (fused)
__global__ void k_scan3() {
    int i = blockIdx.x * blockDim.x + threadIdx.x;
    if (i < NN) {
        int r = g_rowptr[i] + g_bsums[i >> 10];
        g_rowptr[i] = r;
        g_cursor[i] = r;
        int o = g_deg_out[i];
        g_ns[i] = (o > 0) ? rsqrtf((float)o) : 0.f;
        int d = g_deg_in[i];
        g_nd[i] = (d > 0) ? rsqrtf((float)d) : 0.f;
    }
    if (i == 0) g_rowptr[NN] = EE;
}

// scatter with edge-weight computation fused in
__global__ void k_scatter(const int* __restrict__ src, const int* __restrict__ dst,
                          const float* __restrict__ edata,
                          const float* __restrict__ mu, const float* __restrict__ sigma) {
    int e = blockIdx.x * blockDim.x + threadIdx.x;
    if (e < EE) {
        int s = src[e];
        int d = dst[e];
        float ed = edata[e];
        float m = *mu, sg = *sigma;
        float w = (ed == 1.0f) ? 1.0f : expf(-((ed - m) * (ed - m)) / sg);
        float cf = g_ns[s] * w;
        int p = atomicAdd(&g_cursor[d], 1);
        g_csr[p] = make_int2(s, __float_as_int(cf));
    }
}

__global__ void k_copyx(const float* __restrict__ x) {
    size_t i = (size_t)blockIdx.x * blockDim.x + threadIdx.x;
    size_t stride = (size_t)gridDim.x * blockDim.x;
    for (; i < (size_t)NN * 64; i += stride)
        g_hh0[i] = __float2half(x[i]);
}

// ---------------- weight conversion: fp32 [K,N] -> fp16 [N,K] ----------------
struct WConv {
    const float* w[11];
    int K[11];
    int N[11];
};

__global__ void k_wconv(WConv p) {
    int layer = blockIdx.y;
    int K = p.K[layer], N = p.N[layer];
    int tot = K * N;
    const float* w = p.w[layer];
    __half* out = g_w16 + (size_t)layer * WSTRIDE;
    for (int i = blockIdx.x * blockDim.x + threadIdx.x; i < tot; i += gridDim.x * blockDim.x) {
        int k = i / N, n = i % N;
        out[n * K + k] = __float2half(w[i]);
    }
}

// ---------------- aggregation: exact-width mapping ----------------------------
// lanes-per-node = F/8; thread t -> (node = t / lpn, colgroup = t % lpn).
// MODE 0 (spmm-first): read g_hh0, write g_hh1 = acc*nd (fp16)
// MODE 1 (post-gemm):  read g_hh1 (z), write g_hh0 = leaky(acc*nd + b) (fp16)
template<int MODE>
__global__ void k_spmm(int F, int lpn, const float* __restrict__ bias) {
    int t = blockIdx.x * blockDim.x + threadIdx.x;
    int node = t / lpn;
    if (node >= NN) return;
    int c = (t - node * lpn) * 8;

    int beg = g_rowptr[node], end = g_rowptr[node + 1];
    const __half* hsrc = (MODE == 0) ? g_hh0 : g_hh1;
    float acc[8] = {};

    int e = beg;
    for (; e + 1 < end; e += 2) {
        int2 c0 = g_csr[e];
        int2 c1 = g_csr[e + 1];
        int4 v0 = *reinterpret_cast<const int4*>(hsrc + (size_t)c0.x * F + c);
        int4 v1 = *reinterpret_cast<const int4*>(hsrc + (size_t)c1.x * F + c);
        float cf0 = __int_as_float(c0.y);
        float cf1 = __int_as_float(c1.y);
        const __half2* h0 = reinterpret_cast<const __half2*>(&v0);
        const __half2* h1 = reinterpret_cast<const __half2*>(&v1);
        #pragma unroll
        for (int q = 0; q < 4; q++) {
            float2 f0 = __half22float2(h0[q]);
            float2 f1 = __half22float2(h1[q]);
            acc[2 * q + 0] += cf0 * f0.x + cf1 * f1.x;
            acc[2 * q + 1] += cf0 * f0.y + cf1 * f1.y;
        }
    }
    if (e < end) {
        int2 ce = g_csr[e];
        int4 v = *reinterpret_cast<const int4*>(hsrc + (size_t)ce.x * F + c);
        float cf = __int_as_float(ce.y);
        const __half2* hp = reinterpret_cast<const __half2*>(&v);
        #pragma unroll
        for (int q = 0; q < 4; q++) {
            float2 f = __half22float2(hp[q]);
            acc[2 * q + 0] += cf * f.x;
            acc[2 * q + 1] += cf * f.y;
        }
    }

    float nd = g_nd[node];
    __half2 ho[4];
    if (MODE == 0) {
        #pragma unroll
        for (int q = 0; q < 4; q++)
            ho[q] = __floats2half2_rn(acc[2 * q] * nd, acc[2 * q + 1] * nd);
        *reinterpret_cast<int4*>(g_hh1 + (size_t)node * F + c) = *reinterpret_cast<int4*>(ho);
    } else {
        #pragma unroll
        for (int j = 0; j < 8; j++) {
            float v = acc[j] * nd + bias[c + j];
            acc[j] = (v > 0.f) ? v : 0.01f * v;
        }
        #pragma unroll
        for (int q = 0; q < 4; q++)
            ho[q] = __floats2half2_rn(acc[2 * q], acc[2 * q + 1]);
        *reinterpret_cast<int4*>(g_hh0 + (size_t)node * F + c) = *reinterpret_cast<int4*>(ho);
    }
}

// ---------------- tensor-core GEMM (HMMA m16n8k16, fp16 in / fp32 acc) --------
__device__ __forceinline__ void mma16816(float* d, const uint32_t* a, const uint32_t* b) {
    asm volatile(
        "mma.sync.aligned.m16n8k16.row.col.f32.f16.f16.f32 "
        "{%0,%1,%2,%3}, {%4,%5,%6,%7}, {%8,%9}, {%0,%1,%2,%3};\n"
        : "+f"(d[0]), "+f"(d[1]), "+f"(d[2]), "+f"(d[3])
        : "r"(a[0]), "r"(a[1]), "r"(a[2]), "r"(a[3]), "r"(b[0]), "r"(b[1]));
}

#define SA 80  // smem row stride in halves (64 + 16 pad)

template<int MODE, int W32>
__global__ void k_gemm(const float* __restrict__ bias, int layer, int K, int Nn) {
    const __half* A = (MODE == 0) ? g_hh1 : g_hh0;
    const __half* Wl = g_w16 + (size_t)layer * WSTRIDE;
    __shared__ __half As[128 * SA];
    __shared__ __half Bs[64 * SA];

    int tid = threadIdx.x;            // 256
    int lane = tid & 31, wid = tid >> 5;
    int warpM = wid >> 1, warpN = wid & 1;
    int g = lane >> 2, tg2 = (lane & 3) * 2;
    int bm = blockIdx.y * 128, bn = blockIdx.x * 64;

    float acc[2][4][4] = {};

    for (int kc = 0; kc < K; kc += 64) {
        #pragma unroll
        for (int t = 0; t < 4; t++) {
            int idx = tid + t * 256;
            int row = idx >> 3, q = idx & 7;
            int gm = bm + row, o = kc + q * 8;
            int4 v = make_int4(0, 0, 0, 0);
            if (gm < NN && o < K)
                v = *reinterpret_cast<const int4*>(A + (size_t)gm * K + o);
            *reinterpret_cast<int4*>(&As[row * SA + q * 8]) = v;
        }
        #pragma unroll
        for (int t = 0; t < 2; t++) {
            int idx = tid + t * 256;
            int row = idx >> 3, q = idx & 7;
            int gn = bn + row, o = kc + q * 8;
            int4 v = make_int4(0, 0, 0, 0);
            if (gn < Nn && o < K)
                v = *reinterpret_cast<const int4*>(Wl + (size_t)gn * K + o);
            *reinterpret_cast<int4*>(&Bs[row * SA + q * 8]) = v;
        }
        __syncthreads();

        #pragma unroll
        for (int ks = 0; ks < 4; ks++) {
            int kk = ks * 16;
            uint32_t a[2][4], bf[4][2];
            #pragma unroll
            for (int mt = 0; mt < 2; mt++) {
                int r = warpM * 32 + mt * 16 + g;
                a[mt][0] = *reinterpret_cast<const uint32_t*>(&As[r * SA + kk + tg2]);
                a[mt][1] = *reinterpret_cast<const uint32_t*>(&As[(r + 8) * SA + kk + tg2]);
                a[mt][2] = *reinterpret_cast<const uint32_t*>(&As[r * SA + kk + tg2 + 8]);
                a[mt][3] = *reinterpret_cast<const uint32_t*>(&As[(r + 8) * SA + kk + tg2 + 8]);
            }
            #pragma unroll
            for (int nt = 0; nt < 4; nt++) {
                int n = warpN * 32 + nt * 8 + g;
                bf[nt][0] = *reinterpret_cast<const uint32_t*>(&Bs[n * SA + kk + tg2]);
                bf[nt][1] = *reinterpret_cast<const uint32_t*>(&Bs[n * SA + kk + tg2 + 8]);
            }
            #pragma unroll
            for (int mt = 0; mt < 2; mt++)
                #pragma unroll
                for (int nt = 0; nt < 4; nt++)
                    mma16816(acc[mt][nt], a[mt], bf[nt]);
        }
        __syncthreads();
    }

    #pragma unroll
    for (int mt = 0; mt < 2; mt++) {
        #pragma unroll
        for (int nt = 0; nt < 4; nt++) {
            int r0 = bm + warpM * 32 + mt * 16 + g;
            int c0 = bn + warpN * 32 + nt * 8 + tg2;
            float* cc = acc[mt][nt];
            #pragma unroll
            for (int half = 0; half < 2; half++) {
                int r = r0 + half * 8;
                float v0 = cc[half * 2 + 0], v1 = cc[half * 2 + 1];
                if (r < NN && c0 + 1 < Nn) {
                    if (MODE == 0) {
                        v0 += bias[c0]; v1 += bias[c0 + 1];
                        v0 = (v0 > 0.f) ? v0 : 0.01f * v0;
                        v1 = (v1 > 0.f) ? v1 : 0.01f * v1;
                        *reinterpret_cast<__half2*>(g_hh0 + (size_t)r * Nn + c0) =
                            __floats2half2_rn(v0, v1);
                        if (W32) {
                            g_h[(size_t)r * Nn + c0] = v0;
                            g_h[(size_t)r * Nn + c0 + 1] = v1;
                        }
                    } else {
                        *reinterpret_cast<__half2*>(g_hh1 + (size_t)r * Nn + c0) =
                            __floats2half2_rn(v0, v1);
                    }
                }
            }
        }
    }
}

// ---------------- pooling + head ---------------------------------------------
__global__ void k_mean(int F) {
    int j = threadIdx.x;      // blockDim = F (160)
    float acc = 0.f;
    for (int n = blockIdx.x; n < NN; n += gridDim.x)
        acc += g_h[(size_t)n * F + j];
    atomicAdd(&g_mean[j], acc);
}

__global__ void k_head(const float* __restrict__ Wd1, const float* __restrict__ bd1,
                       const float* __restrict__ Wd2, const float* __restrict__ bd2,
                       float* __restrict__ out) {
    __shared__ float hm[160];
    __shared__ float hd[140];
    int t = threadIdx.x;
    if (t < 160) {
        float v = g_mean[t] / (float)NN;
        hm[t] = (v > 0.f) ? v : 0.01f * v;
    }
    __syncthreads();
    if (t < 140) {
        float s = bd1[t];
        for (int k = 0; k < 160; k++) s += hm[k] * Wd1[k * 140 + t];
        hd[t] = (s > 0.f) ? s : 0.01f * s;
    }
    __syncthreads();
    if (t < 2) {
        float s = bd2[t];
        for (int k = 0; k < 140; k++) s += hd[k] * Wd2[k * 2 + t];
        out[t] = 1.0f / (1.0f + expf(-s));
    }
}

// ---------------- launch ------------------------------------------------------
extern "C" void kernel_launch(void* const* d_in, const int* in_sizes, int n_in,
                              void* d_out, int out_size) {
    const float* x     = (const float*)d_in[0];
    const int*   src   = (const int*)d_in[1];
    const int*   dst   = (const int*)d_in[2];
    const float* edata = (const float*)d_in[3];
    const float* W[11];
    const float* b[11];
    for (int i = 0; i < 11; i++) {
        W[i] = (const float*)d_in[4 + 2 * i];
        b[i] = (const float*)d_in[5 + 2 * i];
    }
    const float* Wd1 = (const float*)d_in[26];
    const float* bd1 = (const float*)d_in[27];
    const float* Wd2 = (const float*)d_in[28];
    const float* bd2 = (const float*)d_in[29];
    const float* mu    = (const float*)d_in[30];
    const float* sigma = (const float*)d_in[31];
    float* out = (float*)d_out;

    static const int dims[12] = {64, 80, 160, 112, 160, 176, 96, 144, 96, 128, 96, 160};
    // gemm-first when F_out < F_in (aggregate the narrower tensor)
    static const int gfirst[11] = {0, 0, 1, 0, 0, 1, 0, 1, 0, 1, 0};

    k_zero<<<(NN + 255) / 256, 256>>>();
    k_deg<<<(EE + 255) / 256, 256>>>(src, dst);
    k_scan1<<<SCAN_NB, 1024>>>();
    k_scan2<<<1, 32>>>(SCAN_NB);
    k_scan3<<<(NN + 255) / 256, 256>>>();
    k_scatter<<<(EE + 255) / 256, 256>>>(src, dst, edata, mu, sigma);
    k_copyx<<<4096, 256>>>(x);

    WConv wc;
    for (int i = 0; i < 11; i++) {
        wc.w[i] = W[i];
        wc.K[i] = dims[i];
        wc.N[i] = dims[i + 1];
    }
    k_wconv<<<dim3(121, 11), 256>>>(wc);

    for (int i = 0; i < 11; i++) {
        int Fi = dims[i], Fo = dims[i + 1];
        dim3 grid((Fo + 63) / 64, (NN + 127) / 128);
        if (gfirst[i]) {
            int lpn = Fo >> 3;
            int blocks = (NN * lpn + 255) / 256;
            k_gemm<1, 0><<<grid, 256>>>(nullptr, i, Fi, Fo);
            k_spmm<1><<<blocks, 256>>>(Fo, lpn, b[i]);
        } else {
            int lpn = Fi >> 3;
            int blocks = (NN * lpn + 255) / 256;
            k_spmm<0><<<blocks, 256>>>(Fi, lpn, nullptr);
            if (i == 10)
                k_gemm<0, 1><<<grid, 256>>>(b[i], i, Fi, Fo);
            else
                k_gemm<0, 0><<<grid, 256>>>(b[i], i, Fi, Fo);
        }
    }

    k_mean<<<512, 160>>>(160);
    k_head<<<1, 160>>>(Wd1, bd1, Wd2, bd2, out);
}